// round 5
// baseline (speedup 1.0000x reference)
#include <cuda_runtime.h>
#include <math.h>

#define B_   8
#define M_   1024
#define H_   1024
#define NH_  16
#define HD_  64
#define HID_ 256

// ---------------- scratch (device globals; no allocations allowed) ----------
__device__ float g_q[B_*M_*H_];
__device__ float g_k[B_*M_*H_];
__device__ float g_v[B_*M_*H_];
__device__ float g_g[B_*M_*H_];
__device__ float g_hid[B_*M_*HID_];
__device__ float g_invsig[B_*M_];
__device__ float g_partial[B_*32*H_];
__device__ float g_colsum[B_*H_];

// ---------------- GEMM: Y[r,c] = sum_k X[r,k] W[k,c] + bias[c] --------------
// BM=128, BN=64, BK=16, 256 threads, 8x4 per-thread microtile.
__global__ __launch_bounds__(256) void gemm_bias(
    const float* __restrict__ X, const float* __restrict__ W,
    const float* __restrict__ bias, float* __restrict__ Y,
    int Nc, int Kd)
{
    __shared__ float As[16][128];
    __shared__ float Bs[16][64];
    const int tid = threadIdx.x;
    const int tx = tid & 15, ty = tid >> 4;
    const int r0 = blockIdx.x * 128, n0 = blockIdx.y * 64;
    const int am = tid >> 2, akf = tid & 3;   // A tile load mapping
    const int bk = tid >> 4, bnf = tid & 15;  // B tile load mapping

    float acc[8][4];
#pragma unroll
    for (int i = 0; i < 8; i++)
#pragma unroll
        for (int j = 0; j < 4; j++) acc[i][j] = 0.f;

    for (int k0 = 0; k0 < Kd; k0 += 16) {
        float4 a0 = *(const float4*)(X + (size_t)(r0 + am)      * Kd + k0 + akf * 4);
        float4 a1 = *(const float4*)(X + (size_t)(r0 + am + 64) * Kd + k0 + akf * 4);
        float4 b0 = *(const float4*)(W + (size_t)(k0 + bk) * Nc + n0 + bnf * 4);
        __syncthreads();
        As[akf*4+0][am] = a0.x; As[akf*4+1][am] = a0.y;
        As[akf*4+2][am] = a0.z; As[akf*4+3][am] = a0.w;
        As[akf*4+0][am+64] = a1.x; As[akf*4+1][am+64] = a1.y;
        As[akf*4+2][am+64] = a1.z; As[akf*4+3][am+64] = a1.w;
        *(float4*)(&Bs[bk][bnf*4]) = b0;
        __syncthreads();
#pragma unroll
        for (int kk = 0; kk < 16; kk++) {
            float a[8], bb[4];
#pragma unroll
            for (int i = 0; i < 8; i++) a[i] = As[kk][ty*8 + i];
#pragma unroll
            for (int j = 0; j < 4; j++) bb[j] = Bs[kk][tx*4 + j];
#pragma unroll
            for (int i = 0; i < 8; i++)
#pragma unroll
                for (int j = 0; j < 4; j++)
                    acc[i][j] = fmaf(a[i], bb[j], acc[i][j]);
        }
    }
    float4 bv = *(const float4*)(bias + n0 + tx*4);
#pragma unroll
    for (int i = 0; i < 8; i++) {
        float4 o;
        o.x = acc[i][0] + bv.x; o.y = acc[i][1] + bv.y;
        o.z = acc[i][2] + bv.z; o.w = acc[i][3] + bv.w;
        *(float4*)(Y + (size_t)(r0 + ty*8 + i) * Nc + n0 + tx*4) = o;
    }
}

// ---------------- sigma: softplus(relu(hid) @ Wu2 + bu2) + 1e-6 -------------
__global__ __launch_bounds__(256) void sigma_finish(
    const float* __restrict__ hid, const float* __restrict__ Wu2,
    const float* __restrict__ bu2, float* __restrict__ sig_out,
    float* __restrict__ invsig)
{
    const int row = blockIdx.x, t = threadIdx.x;
    __shared__ float red[256];
    float h = hid[(size_t)row * HID_ + t];
    red[t] = fmaxf(h, 0.f) * Wu2[t];
    __syncthreads();
    for (int s = 128; s > 0; s >>= 1) {
        if (t < s) red[t] += red[t + s];
        __syncthreads();
    }
    if (t == 0) {
        float tv = red[0] + bu2[0];
        float sp = (tv > 0.f) ? tv + log1pf(expf(-tv)) : log1pf(expf(tv));
        float sg = sp + 1e-6f;
        sig_out[row] = sg;
        invsig[row] = 1.f / sg;
    }
}

// ---------------- fused attention: scores -> softmax -> attn out + ctx*g ----
#define SP  1032   // score row pitch (floats), conflict-padded, %4==0
#define KSP 257    // k-transposed row pitch

__global__ __launch_bounds__(256) void attn_kernel(
    const float* __restrict__ qb, const float* __restrict__ kb,
    const float* __restrict__ vb, const float* __restrict__ gb,
    const float* __restrict__ invsig,
    float* __restrict__ attn_out, float* __restrict__ partial)
{
    extern __shared__ float smdyn[];
    float* ss = smdyn;              // [32][SP]  scores / attn
    float* qs = ss + 32 * SP;       // [32][64]  q tile, later ctx*g
    float* kv = qs + 32 * 64;       // k chunk [64][KSP] transposed / v chunk [256][64]
    __shared__ float ism[32];
    __shared__ float isn[M_];

    const int mt = blockIdx.x, h = blockIdx.y, b = blockIdx.z;
    const int m0 = mt * 32;
    const int tid = threadIdx.x;

    // q tile [32][64]
    for (int i = tid; i < 32 * 16; i += 256) {
        int m = i >> 4, f = i & 15;
        *(float4*)(qs + m * 64 + f * 4) =
            *(const float4*)(qb + (((size_t)(b * M_ + m0 + m)) * NH_ + h) * HD_ + f * 4);
    }
    if (tid < 32) ism[tid] = invsig[b * M_ + m0 + tid];
    for (int i = tid; i < M_; i += 256) isn[i] = invsig[b * M_ + i];

    const int tn5 = tid & 31;   // n lane within chunk
    const int tmq = tid >> 5;   // m group (whole warp shares it)

    // ----- scores: 4 chunks of 256 n -----
    for (int nc = 0; nc < 4; nc++) {
        const int nb = nc * 256;
        // load k chunk transposed: kv[d][n]
        for (int it = 0; it < 16; it++) {
            int idx = tid + 256 * it;
            int n = idx >> 4, f = idx & 15;
            float4 kx = *(const float4*)(kb + (((size_t)(b * M_ + nb + n)) * NH_ + h) * HD_ + f * 4);
            kv[(f*4+0)*KSP + n] = kx.x;
            kv[(f*4+1)*KSP + n] = kx.y;
            kv[(f*4+2)*KSP + n] = kx.z;
            kv[(f*4+3)*KSP + n] = kx.w;
        }
        __syncthreads();
        float acc[4][8];
#pragma unroll
        for (int i = 0; i < 4; i++)
#pragma unroll
            for (int j = 0; j < 8; j++) acc[i][j] = 0.f;
#pragma unroll 8
        for (int d = 0; d < 64; d++) {
            float a[4], bb[8];
#pragma unroll
            for (int i = 0; i < 4; i++) a[i] = qs[(tmq + 8*i) * 64 + d];
#pragma unroll
            for (int j = 0; j < 8; j++) bb[j] = kv[d * KSP + tn5 + 32*j];
#pragma unroll
            for (int i = 0; i < 4; i++)
#pragma unroll
                for (int j = 0; j < 8; j++)
                    acc[i][j] = fmaf(a[i], bb[j], acc[i][j]);
        }
#pragma unroll
        for (int i = 0; i < 4; i++) {
            int m = tmq + 8*i;
            float sm_ = 0.125f * ism[m];
#pragma unroll
            for (int j = 0; j < 8; j++) {
                int n = tn5 + 32*j;
                ss[m * SP + nb + n] = acc[i][j] * sm_ * isn[nb + n];
            }
        }
        __syncthreads();
    }

    // ----- softmax per row (8 warps x 4 rows), write attn to gmem -----
    const int warp = tid >> 5, lane = tid & 31;
    for (int rr = 0; rr < 4; rr++) {
        int m = warp + 8 * rr;
        float* row = ss + m * SP;
        float mx = -1e30f;
#pragma unroll
        for (int i = 0; i < 32; i++) mx = fmaxf(mx, row[lane + 32*i]);
        for (int o = 16; o > 0; o >>= 1) mx = fmaxf(mx, __shfl_xor_sync(0xffffffffu, mx, o));
        float sum = 0.f;
#pragma unroll
        for (int i = 0; i < 32; i++) {
            float e = __expf(row[lane + 32*i] - mx);
            row[lane + 32*i] = e;
            sum += e;
        }
        for (int o = 16; o > 0; o >>= 1) sum += __shfl_xor_sync(0xffffffffu, sum, o);
        float inv = 1.f / sum;
        float* orow = attn_out + (((size_t)(b * NH_ + h)) * M_ + m0 + m) * M_;
#pragma unroll
        for (int c = 0; c < 8; c++) {
            float4 v4 = *(float4*)(row + c*128 + lane*4);
            v4.x *= inv; v4.y *= inv; v4.z *= inv; v4.w *= inv;
            *(float4*)(row + c*128 + lane*4) = v4;
            *(float4*)(orow + c*128 + lane*4) = v4;
        }
    }
    __syncthreads();

    // ----- ctx = attn @ v : each thread does rows {tmm, tmm+16}, d = td*4..+3
    const int td = tid & 15;
    const int tmm = tid >> 4;
    float4 a0 = {0.f,0.f,0.f,0.f}, a1 = {0.f,0.f,0.f,0.f};
    for (int nc = 0; nc < 4; nc++) {
        const int nb = nc * 256;
        for (int it = 0; it < 16; it++) {
            int idx = tid + 256 * it;
            int n = idx >> 4, f = idx & 15;
            *(float4*)(kv + n * 64 + f * 4) =
                *(const float4*)(vb + (((size_t)(b * M_ + nb + n)) * NH_ + h) * HD_ + f * 4);
        }
        __syncthreads();
        for (int n = 0; n < 256; n++) {
            float s0 = ss[tmm * SP + nb + n];
            float s1 = ss[(tmm + 16) * SP + nb + n];
            float4 vv = *(float4*)(kv + n * 64 + td * 4);
            a0.x = fmaf(s0, vv.x, a0.x); a0.y = fmaf(s0, vv.y, a0.y);
            a0.z = fmaf(s0, vv.z, a0.z); a0.w = fmaf(s0, vv.w, a0.w);
            a1.x = fmaf(s1, vv.x, a1.x); a1.y = fmaf(s1, vv.y, a1.y);
            a1.z = fmaf(s1, vv.z, a1.z); a1.w = fmaf(s1, vv.w, a1.w);
        }
        __syncthreads();
    }

    // ----- multiply by sigmoid(g), stash in qs, reduce over m for col sums --
    {
        float4 g0 = *(const float4*)(gb + (((size_t)(b * M_ + m0 + tmm))      * NH_ + h) * HD_ + td * 4);
        float4 g1 = *(const float4*)(gb + (((size_t)(b * M_ + m0 + tmm + 16)) * NH_ + h) * HD_ + td * 4);
        // sigmoid (was missing in R2 -> caused z rel_err 0.43)
        g0.x = 1.f / (1.f + __expf(-g0.x)); g0.y = 1.f / (1.f + __expf(-g0.y));
        g0.z = 1.f / (1.f + __expf(-g0.z)); g0.w = 1.f / (1.f + __expf(-g0.w));
        g1.x = 1.f / (1.f + __expf(-g1.x)); g1.y = 1.f / (1.f + __expf(-g1.y));
        g1.z = 1.f / (1.f + __expf(-g1.z)); g1.w = 1.f / (1.f + __expf(-g1.w));
        a0.x *= g0.x; a0.y *= g0.y; a0.z *= g0.z; a0.w *= g0.w;
        a1.x *= g1.x; a1.y *= g1.y; a1.z *= g1.z; a1.w *= g1.w;
        *(float4*)(qs + tmm * 64 + td * 4) = a0;
        *(float4*)(qs + (tmm + 16) * 64 + td * 4) = a1;
    }
    __syncthreads();
    if (tid < 64) {
        float s = 0.f;
#pragma unroll
        for (int m = 0; m < 32; m++) s += qs[m * 64 + tid];
        partial[((size_t)(b * 32 + mt)) * H_ + h * 64 + tid] = s;
    }
}

// ---------------- column-sum reduce (mean over m) ---------------------------
__global__ __launch_bounds__(256) void colsum_kernel(
    const float* __restrict__ partial, float* __restrict__ colsum)
{
    int b = blockIdx.y;
    int c = blockIdx.x * 256 + threadIdx.x;
    float s = 0.f;
#pragma unroll
    for (int t = 0; t < 32; t++) s += partial[((size_t)(b * 32 + t)) * H_ + c];
    colsum[b * H_ + c] = s * (1.f / 1024.f);
}

// ---------------- z = mean @ Wo + bo ----------------------------------------
__global__ __launch_bounds__(128) void zout_kernel(
    const float* __restrict__ colsum, const float* __restrict__ Wo,
    const float* __restrict__ bo, float* __restrict__ z)
{
    int b = blockIdx.y;
    int n = blockIdx.x * 128 + threadIdx.x;
    __shared__ float cs[H_];
    for (int i = threadIdx.x; i < H_; i += 128) cs[i] = colsum[b * H_ + i];
    __syncthreads();
    float acc = bo[n];
    for (int i = 0; i < H_; i++) acc = fmaf(cs[i], Wo[(size_t)i * H_ + n], acc);
    z[b * H_ + n] = acc;
}

// ---------------------------------------------------------------------------
extern "C" void kernel_launch(void* const* d_in, const int* in_sizes, int n_in,
                              void* d_out, int out_size)
{
    const float* x   = (const float*)d_in[0];
    const float* Wq  = (const float*)d_in[1];
    const float* bq  = (const float*)d_in[2];
    const float* Wk  = (const float*)d_in[3];
    const float* bk  = (const float*)d_in[4];
    const float* Wv  = (const float*)d_in[5];
    const float* bv  = (const float*)d_in[6];
    const float* Wg  = (const float*)d_in[7];
    const float* bg  = (const float*)d_in[8];
    const float* Wo  = (const float*)d_in[9];
    const float* bo  = (const float*)d_in[10];
    const float* Wu1 = (const float*)d_in[11];
    const float* bu1 = (const float*)d_in[12];
    const float* Wu2 = (const float*)d_in[13];
    const float* bu2 = (const float*)d_in[14];

    float* out      = (float*)d_out;
    float* z_out    = out;                                  // [8,1024]
    float* attn_out = out + B_ * H_;                        // [8,16,1024,1024]
    float* sig_out  = out + (size_t)out_size - B_ * M_;     // [8,1024]

    float *qp, *kp, *vp, *gp, *hp, *isp, *pp, *cp;
    cudaGetSymbolAddress((void**)&qp, g_q);
    cudaGetSymbolAddress((void**)&kp, g_k);
    cudaGetSymbolAddress((void**)&vp, g_v);
    cudaGetSymbolAddress((void**)&gp, g_g);
    cudaGetSymbolAddress((void**)&hp, g_hid);
    cudaGetSymbolAddress((void**)&isp, g_invsig);
    cudaGetSymbolAddress((void**)&pp, g_partial);
    cudaGetSymbolAddress((void**)&cp, g_colsum);

    const int DYN = (32 * SP + 32 * 64 + 64 * KSP) * (int)sizeof(float); // 206080 B
    cudaFuncSetAttribute(attn_kernel, cudaFuncAttributeMaxDynamicSharedMemorySize, DYN);

    dim3 gproj(64, 16), ghid(64, 4);
    gemm_bias<<<gproj, 256>>>(x, Wq, bq, qp, H_, H_);
    gemm_bias<<<gproj, 256>>>(x, Wk, bk, kp, H_, H_);
    gemm_bias<<<gproj, 256>>>(x, Wv, bv, vp, H_, H_);
    gemm_bias<<<gproj, 256>>>(x, Wg, bg, gp, H_, H_);
    gemm_bias<<<ghid, 256>>>(x, Wu1, bu1, hp, HID_, H_);

    sigma_finish<<<B_ * M_, 256>>>(hp, Wu2, bu2, sig_out, isp);

    attn_kernel<<<dim3(32, 16, 8), 256, DYN>>>(qp, kp, vp, gp, isp, attn_out, pp);

    colsum_kernel<<<dim3(4, 8), 256>>>(pp, cp);
    zout_kernel<<<dim3(8, 8), 128>>>(cp, Wo, bo, z_out);
}

// round 8
// speedup vs baseline: 1.1343x; 1.1343x over previous
#include <cuda_runtime.h>
#include <cuda_bf16.h>
#include <cstdint>
#include <cstring>
#include <math.h>

#define B_   8
#define M_   1024
#define H_   1024
#define NH_  16
#define HD_  64
#define HID_ 256

// ---------------- scratch (device globals; no allocations allowed) ----------
__device__ float g_q[B_*M_*H_];
__device__ float g_k[B_*M_*H_];
__device__ float g_v[B_*M_*H_];
__device__ float g_g[B_*M_*H_];
__device__ float g_hid[B_*M_*HID_];
__device__ float g_invsig[B_*M_];
__device__ float g_partial[B_*32*H_];
__device__ float g_colsum[B_*H_];

// ============================================================================
// Tensor-core GEMM with split-bf16 (hi/lo, 3-term) compensation.
// Y[r,c] = sum_k X[r,k] W[k,c] + bias[c]    (fp32 in/out, ~1e-5 accuracy)
// BM=128, BN=128, BK=32, 256 threads, warp tile 64x32, mma.m16n8k16.bf16.
// ============================================================================
#define PITCH_B32 20            // b32 per smem row (32 bf16 = 16 b32, pad to 20)
#define PITCH_B16 40
#define TILE_B32  (128 * PITCH_B32)   // 2560 words per tile
#define GEMM_DYN  (8 * TILE_B32 * 4)  // 2 bufs x (Ahi,Alo,Bhi,Blo) = 81920 B

// split (a,b) into hi bf16 pair + lo (residual) bf16 pair — intrinsics only,
// no bf16 constructors/conversions (robust to __CUDA_NO_BFLOAT16* macros).
__device__ __forceinline__ void split2(float a, float b, unsigned& hi, unsigned& lo) {
    __nv_bfloat162 h = __floats2bfloat162_rn(a, b);
    float ra = a - __low2float(h);
    float rb = b - __high2float(h);
    __nv_bfloat162 l = __floats2bfloat162_rn(ra, rb);
    unsigned uh, ul;
    memcpy(&uh, &h, 4);
    memcpy(&ul, &l, 4);
    hi = uh; lo = ul;
}

__device__ __forceinline__ void ldm_x4(unsigned* r, unsigned addr) {
    asm volatile("ldmatrix.sync.aligned.m8n8.x4.shared.b16 {%0,%1,%2,%3}, [%4];\n"
        : "=r"(r[0]), "=r"(r[1]), "=r"(r[2]), "=r"(r[3]) : "r"(addr));
}

__device__ __forceinline__ void mma16816(float* d, const unsigned* a,
                                         unsigned b0, unsigned b1) {
    asm volatile(
        "mma.sync.aligned.m16n8k16.row.col.f32.bf16.bf16.f32 "
        "{%0,%1,%2,%3}, {%4,%5,%6,%7}, {%8,%9}, {%0,%1,%2,%3};\n"
        : "+f"(d[0]), "+f"(d[1]), "+f"(d[2]), "+f"(d[3])
        : "r"(a[0]), "r"(a[1]), "r"(a[2]), "r"(a[3]), "r"(b0), "r"(b1));
}

// stage one BK=32 slab of X and W into smem as bf16 hi/lo tiles
__device__ __forceinline__ void gemm_stage(
    const float* __restrict__ X, const float* __restrict__ W, int Nc,
    int r0, int n0, int k0,
    unsigned* __restrict__ Ahi, unsigned* __restrict__ Alo,
    unsigned* __restrict__ Bhi, unsigned* __restrict__ Blo, int tid)
{
    // ---- A: 128 m x 32 k  (X row-major, k contiguous) ----
#pragma unroll
    for (int it = 0; it < 4; it++) {
        int t = tid + it * 256;
        int m = t >> 3, kq = t & 7;            // kq*4 = k offset
        float4 v = *(const float4*)(X + (size_t)(r0 + m) * H_ + k0 + kq * 4);
        unsigned h0, l0, h1, l1;
        split2(v.x, v.y, h0, l0);
        split2(v.z, v.w, h1, l1);
        uint2 hp; hp.x = h0; hp.y = h1;
        uint2 lp; lp.x = l0; lp.y = l1;
        *(uint2*)(Ahi + m * PITCH_B32 + kq * 2) = hp;
        *(uint2*)(Alo + m * PITCH_B32 + kq * 2) = lp;
    }
    // ---- B: 128 n x 32 k transposed from W[k][n] ----
#pragma unroll
    for (int it = 0; it < 2; it++) {
        int t = tid + it * 256;
        int nq = t & 31, kp = t >> 5;          // kp = k pair index 0..15
        const float* w0 = W + (size_t)(k0 + 2 * kp) * Nc + n0 + nq * 4;
        float4 u = *(const float4*)(w0);
        float4 v = *(const float4*)(w0 + Nc);
        float uu[4] = {u.x, u.y, u.z, u.w};
        float vv[4] = {v.x, v.y, v.z, v.w};
#pragma unroll
        for (int j = 0; j < 4; j++) {
            unsigned hh, ll;
            split2(uu[j], vv[j], hh, ll);
            int n = nq * 4 + j;
            Bhi[n * PITCH_B32 + kp] = hh;
            Blo[n * PITCH_B32 + kp] = ll;
        }
    }
}

__global__ __launch_bounds__(256) void gemm_tc(
    const float* __restrict__ X, const float* __restrict__ W,
    const float* __restrict__ bias, float* __restrict__ Y, int Nc)
{
    extern __shared__ unsigned smw[];
    const int tid = threadIdx.x;
    const int lane = tid & 31, warp = tid >> 5;
    const int wm = warp >> 2, wn = warp & 3;
    const int r0 = blockIdx.x * 128, n0 = blockIdx.y * 128;

    // tile pointers: [buf][Ahi,Alo,Bhi,Blo]
    unsigned* tile[2][4];
#pragma unroll
    for (int bi = 0; bi < 2; bi++)
#pragma unroll
        for (int vi = 0; vi < 4; vi++) tile[bi][vi] = smw + (bi * 4 + vi) * TILE_B32;

    const unsigned sbase = (unsigned)__cvta_generic_to_shared(smw);
    unsigned toff[2][4];
#pragma unroll
    for (int bi = 0; bi < 2; bi++)
#pragma unroll
        for (int vi = 0; vi < 4; vi++) toff[bi][vi] = (unsigned)((bi * 4 + vi) * TILE_B32 * 4);

    // per-lane ldmatrix offsets (in b16 units)
    const unsigned a_lane = (unsigned)((lane & 15) * PITCH_B16 + (lane >> 4) * 8);
    const unsigned b_lane = (unsigned)(((lane & 7) + ((lane >> 4) & 1) * 8) * PITCH_B16
                                       + ((lane >> 3) & 1) * 8);

    float acc[4][4][4];
#pragma unroll
    for (int i = 0; i < 4; i++)
#pragma unroll
        for (int j = 0; j < 4; j++)
#pragma unroll
            for (int c = 0; c < 4; c++) acc[i][j][c] = 0.f;

    gemm_stage(X, W, Nc, r0, n0, 0, tile[0][0], tile[0][1], tile[0][2], tile[0][3], tid);
    __syncthreads();

    const int NKC = H_ / 32;
    for (int kc = 0; kc < NKC; kc++) {
        const int cur = kc & 1;
        if (kc + 1 < NKC)
            gemm_stage(X, W, Nc, r0, n0, (kc + 1) * 32,
                       tile[cur ^ 1][0], tile[cur ^ 1][1],
                       tile[cur ^ 1][2], tile[cur ^ 1][3], tid);

#pragma unroll
        for (int ks = 0; ks < 2; ks++) {
            unsigned af[4][4], bfr[2][4];
            const unsigned kso = (unsigned)(ks * 16);
            // --- Ahi x Bhi ---
#pragma unroll
            for (int mt = 0; mt < 4; mt++)
                ldm_x4(af[mt], sbase + toff[cur][0] +
                       (a_lane + (unsigned)((wm * 64 + mt * 16) * PITCH_B16) + kso) * 2);
#pragma unroll
            for (int np = 0; np < 2; np++)
                ldm_x4(bfr[np], sbase + toff[cur][2] +
                       (b_lane + (unsigned)((wn * 32 + np * 16) * PITCH_B16) + kso) * 2);
#pragma unroll
            for (int mt = 0; mt < 4; mt++)
#pragma unroll
                for (int nt = 0; nt < 4; nt++)
                    mma16816(acc[mt][nt], af[mt],
                             bfr[nt >> 1][(nt & 1) * 2], bfr[nt >> 1][(nt & 1) * 2 + 1]);
            // --- Ahi x Blo ---
#pragma unroll
            for (int np = 0; np < 2; np++)
                ldm_x4(bfr[np], sbase + toff[cur][3] +
                       (b_lane + (unsigned)((wn * 32 + np * 16) * PITCH_B16) + kso) * 2);
#pragma unroll
            for (int mt = 0; mt < 4; mt++)
#pragma unroll
                for (int nt = 0; nt < 4; nt++)
                    mma16816(acc[mt][nt], af[mt],
                             bfr[nt >> 1][(nt & 1) * 2], bfr[nt >> 1][(nt & 1) * 2 + 1]);
            // --- Alo x Bhi ---
#pragma unroll
            for (int mt = 0; mt < 4; mt++)
                ldm_x4(af[mt], sbase + toff[cur][1] +
                       (a_lane + (unsigned)((wm * 64 + mt * 16) * PITCH_B16) + kso) * 2);
#pragma unroll
            for (int np = 0; np < 2; np++)
                ldm_x4(bfr[np], sbase + toff[cur][2] +
                       (b_lane + (unsigned)((wn * 32 + np * 16) * PITCH_B16) + kso) * 2);
#pragma unroll
            for (int mt = 0; mt < 4; mt++)
#pragma unroll
                for (int nt = 0; nt < 4; nt++)
                    mma16816(acc[mt][nt], af[mt],
                             bfr[nt >> 1][(nt & 1) * 2], bfr[nt >> 1][(nt & 1) * 2 + 1]);
        }
        __syncthreads();
    }

    // epilogue: bias + store
    const int g = lane >> 2, tg = lane & 3;
#pragma unroll
    for (int mt = 0; mt < 4; mt++) {
#pragma unroll
        for (int nt = 0; nt < 4; nt++) {
            int row = r0 + wm * 64 + mt * 16 + g;
            int col = n0 + wn * 32 + nt * 8 + tg * 2;
            float bx = bias[col], by = bias[col + 1];
            float2 o0; o0.x = acc[mt][nt][0] + bx; o0.y = acc[mt][nt][1] + by;
            float2 o1; o1.x = acc[mt][nt][2] + bx; o1.y = acc[mt][nt][3] + by;
            *(float2*)(Y + (size_t)row * Nc + col) = o0;
            *(float2*)(Y + (size_t)(row + 8) * Nc + col) = o1;
        }
    }
}

// ---------------- sigma: softplus(relu(hid) @ Wu2 + bu2) + 1e-6 -------------
__global__ __launch_bounds__(256) void sigma_finish(
    const float* __restrict__ hid, const float* __restrict__ Wu2,
    const float* __restrict__ bu2, float* __restrict__ sig_out,
    float* __restrict__ invsig)
{
    const int row = blockIdx.x, t = threadIdx.x;
    __shared__ float red[256];
    float h = hid[(size_t)row * HID_ + t];
    red[t] = fmaxf(h, 0.f) * Wu2[t];
    __syncthreads();
    for (int s = 128; s > 0; s >>= 1) {
        if (t < s) red[t] += red[t + s];
        __syncthreads();
    }
    if (t == 0) {
        float tv = red[0] + bu2[0];
        float sp = (tv > 0.f) ? tv + log1pf(expf(-tv)) : log1pf(expf(tv));
        float sg = sp + 1e-6f;
        sig_out[row] = sg;
        invsig[row] = 1.f / sg;
    }
}

// ---------------- fused attention: scores -> softmax -> attn out + ctx*g ----
#define SP  1032   // score row pitch (floats), conflict-padded, %4==0
#define KSP 257    // k-transposed row pitch

__global__ __launch_bounds__(256) void attn_kernel(
    const float* __restrict__ qb, const float* __restrict__ kb,
    const float* __restrict__ vb, const float* __restrict__ gb,
    const float* __restrict__ invsig,
    float* __restrict__ attn_out, float* __restrict__ partial)
{
    extern __shared__ float smdyn[];
    float* ss = smdyn;              // [32][SP]  scores / attn
    float* qs = ss + 32 * SP;       // [32][64]  q tile, later ctx*g
    float* kv = qs + 32 * 64;       // k chunk [64][KSP] transposed / v chunk [256][64]
    __shared__ float ism[32];
    __shared__ float isn[M_];

    const int mt = blockIdx.x, h = blockIdx.y, b = blockIdx.z;
    const int m0 = mt * 32;
    const int tid = threadIdx.x;

    for (int i = tid; i < 32 * 16; i += 256) {
        int m = i >> 4, f = i & 15;
        *(float4*)(qs + m * 64 + f * 4) =
            *(const float4*)(qb + (((size_t)(b * M_ + m0 + m)) * NH_ + h) * HD_ + f * 4);
    }
    if (tid < 32) ism[tid] = invsig[b * M_ + m0 + tid];
    for (int i = tid; i < M_; i += 256) isn[i] = invsig[b * M_ + i];

    const int tn5 = tid & 31;
    const int tmq = tid >> 5;

    for (int nc = 0; nc < 4; nc++) {
        const int nb = nc * 256;
        for (int it = 0; it < 16; it++) {
            int idx = tid + 256 * it;
            int n = idx >> 4, f = idx & 15;
            float4 kx = *(const float4*)(kb + (((size_t)(b * M_ + nb + n)) * NH_ + h) * HD_ + f * 4);
            kv[(f*4+0)*KSP + n] = kx.x;
            kv[(f*4+1)*KSP + n] = kx.y;
            kv[(f*4+2)*KSP + n] = kx.z;
            kv[(f*4+3)*KSP + n] = kx.w;
        }
        __syncthreads();
        float acc[4][8];
#pragma unroll
        for (int i = 0; i < 4; i++)
#pragma unroll
            for (int j = 0; j < 8; j++) acc[i][j] = 0.f;
#pragma unroll 8
        for (int d = 0; d < 64; d++) {
            float a[4], bb[8];
#pragma unroll
            for (int i = 0; i < 4; i++) a[i] = qs[(tmq + 8*i) * 64 + d];
#pragma unroll
            for (int j = 0; j < 8; j++) bb[j] = kv[d * KSP + tn5 + 32*j];
#pragma unroll
            for (int i = 0; i < 4; i++)
#pragma unroll
                for (int j = 0; j < 8; j++)
                    acc[i][j] = fmaf(a[i], bb[j], acc[i][j]);
        }
#pragma unroll
        for (int i = 0; i < 4; i++) {
            int m = tmq + 8*i;
            float sm_ = 0.125f * ism[m];
#pragma unroll
            for (int j = 0; j < 8; j++) {
                int n = tn5 + 32*j;
                ss[m * SP + nb + n] = acc[i][j] * sm_ * isn[nb + n];
            }
        }
        __syncthreads();
    }

    const int warp = tid >> 5, lane = tid & 31;
    for (int rr = 0; rr < 4; rr++) {
        int m = warp + 8 * rr;
        float* row = ss + m * SP;
        float mx = -1e30f;
#pragma unroll
        for (int i = 0; i < 32; i++) mx = fmaxf(mx, row[lane + 32*i]);
        for (int o = 16; o > 0; o >>= 1) mx = fmaxf(mx, __shfl_xor_sync(0xffffffffu, mx, o));
        float sum = 0.f;
#pragma unroll
        for (int i = 0; i < 32; i++) {
            float e = __expf(row[lane + 32*i] - mx);
            row[lane + 32*i] = e;
            sum += e;
        }
        for (int o = 16; o > 0; o >>= 1) sum += __shfl_xor_sync(0xffffffffu, sum, o);
        float inv = 1.f / sum;
        float* orow = attn_out + (((size_t)(b * NH_ + h)) * M_ + m0 + m) * M_;
#pragma unroll
        for (int c = 0; c < 8; c++) {
            float4 v4 = *(float4*)(row + c*128 + lane*4);
            v4.x *= inv; v4.y *= inv; v4.z *= inv; v4.w *= inv;
            *(float4*)(row + c*128 + lane*4) = v4;
            *(float4*)(orow + c*128 + lane*4) = v4;
        }
    }
    __syncthreads();

    const int td = tid & 15;
    const int tmm = tid >> 4;
    float4 a0 = {0.f,0.f,0.f,0.f}, a1 = {0.f,0.f,0.f,0.f};
    for (int nc = 0; nc < 4; nc++) {
        const int nb = nc * 256;
        for (int it = 0; it < 16; it++) {
            int idx = tid + 256 * it;
            int n = idx >> 4, f = idx & 15;
            *(float4*)(kv + n * 64 + f * 4) =
                *(const float4*)(vb + (((size_t)(b * M_ + nb + n)) * NH_ + h) * HD_ + f * 4);
        }
        __syncthreads();
        for (int n = 0; n < 256; n++) {
            float s0 = ss[tmm * SP + nb + n];
            float s1 = ss[(tmm + 16) * SP + nb + n];
            float4 vv = *(float4*)(kv + n * 64 + td * 4);
            a0.x = fmaf(s0, vv.x, a0.x); a0.y = fmaf(s0, vv.y, a0.y);
            a0.z = fmaf(s0, vv.z, a0.z); a0.w = fmaf(s0, vv.w, a0.w);
            a1.x = fmaf(s1, vv.x, a1.x); a1.y = fmaf(s1, vv.y, a1.y);
            a1.z = fmaf(s1, vv.z, a1.z); a1.w = fmaf(s1, vv.w, a1.w);
        }
        __syncthreads();
    }

    {
        float4 g0 = *(const float4*)(gb + (((size_t)(b * M_ + m0 + tmm))      * NH_ + h) * HD_ + td * 4);
        float4 g1 = *(const float4*)(gb + (((size_t)(b * M_ + m0 + tmm + 16)) * NH_ + h) * HD_ + td * 4);
        g0.x = 1.f / (1.f + __expf(-g0.x)); g0.y = 1.f / (1.f + __expf(-g0.y));
        g0.z = 1.f / (1.f + __expf(-g0.z)); g0.w = 1.f / (1.f + __expf(-g0.w));
        g1.x = 1.f / (1.f + __expf(-g1.x)); g1.y = 1.f / (1.f + __expf(-g1.y));
        g1.z = 1.f / (1.f + __expf(-g1.z)); g1.w = 1.f / (1.f + __expf(-g1.w));
        a0.x *= g0.x; a0.y *= g0.y; a0.z *= g0.z; a0.w *= g0.w;
        a1.x *= g1.x; a1.y *= g1.y; a1.z *= g1.z; a1.w *= g1.w;
        *(float4*)(qs + tmm * 64 + td * 4) = a0;
        *(float4*)(qs + (tmm + 16) * 64 + td * 4) = a1;
    }
    __syncthreads();
    if (tid < 64) {
        float s = 0.f;
#pragma unroll
        for (int m = 0; m < 32; m++) s += qs[m * 64 + tid];
        partial[((size_t)(b * 32 + mt)) * H_ + h * 64 + tid] = s;
    }
}

// ---------------- column-sum reduce (mean over m) ---------------------------
__global__ __launch_bounds__(256) void colsum_kernel(
    const float* __restrict__ partial, float* __restrict__ colsum)
{
    int b = blockIdx.y;
    int c = blockIdx.x * 256 + threadIdx.x;
    float s = 0.f;
#pragma unroll
    for (int t = 0; t < 32; t++) s += partial[((size_t)(b * 32 + t)) * H_ + c];
    colsum[b * H_ + c] = s * (1.f / 1024.f);
}

// ---------------- z = mean @ Wo + bo ----------------------------------------
__global__ __launch_bounds__(128) void zout_kernel(
    const float* __restrict__ colsum, const float* __restrict__ Wo,
    const float* __restrict__ bo, float* __restrict__ z)
{
    int b = blockIdx.y;
    int n = blockIdx.x * 128 + threadIdx.x;
    __shared__ float cs[H_];
    for (int i = threadIdx.x; i < H_; i += 128) cs[i] = colsum[b * H_ + i];
    __syncthreads();
    float acc = bo[n];
    for (int i = 0; i < H_; i++) acc = fmaf(cs[i], Wo[(size_t)i * H_ + n], acc);
    z[b * H_ + n] = acc;
}

// ---------------------------------------------------------------------------
extern "C" void kernel_launch(void* const* d_in, const int* in_sizes, int n_in,
                              void* d_out, int out_size)
{
    const float* x   = (const float*)d_in[0];
    const float* Wq  = (const float*)d_in[1];
    const float* bq  = (const float*)d_in[2];
    const float* Wk  = (const float*)d_in[3];
    const float* bk  = (const float*)d_in[4];
    const float* Wv  = (const float*)d_in[5];
    const float* bv  = (const float*)d_in[6];
    const float* Wg  = (const float*)d_in[7];
    const float* bg  = (const float*)d_in[8];
    const float* Wo  = (const float*)d_in[9];
    const float* bo  = (const float*)d_in[10];
    const float* Wu1 = (const float*)d_in[11];
    const float* bu1 = (const float*)d_in[12];
    const float* Wu2 = (const float*)d_in[13];
    const float* bu2 = (const float*)d_in[14];

    float* out      = (float*)d_out;
    float* z_out    = out;                                  // [8,1024]
    float* attn_out = out + B_ * H_;                        // [8,16,1024,1024]
    float* sig_out  = out + (size_t)out_size - B_ * M_;     // [8,1024]

    float *qp, *kp, *vp, *gp, *hp, *isp, *pp, *cp;
    cudaGetSymbolAddress((void**)&qp, g_q);
    cudaGetSymbolAddress((void**)&kp, g_k);
    cudaGetSymbolAddress((void**)&vp, g_v);
    cudaGetSymbolAddress((void**)&gp, g_g);
    cudaGetSymbolAddress((void**)&hp, g_hid);
    cudaGetSymbolAddress((void**)&isp, g_invsig);
    cudaGetSymbolAddress((void**)&pp, g_partial);
    cudaGetSymbolAddress((void**)&cp, g_colsum);

    const int DYN = (32 * SP + 32 * 64 + 64 * KSP) * (int)sizeof(float); // 206080 B
    cudaFuncSetAttribute(attn_kernel, cudaFuncAttributeMaxDynamicSharedMemorySize, DYN);
    cudaFuncSetAttribute(gemm_tc, cudaFuncAttributeMaxDynamicSharedMemorySize, GEMM_DYN);

    dim3 gproj(64, 8);
    dim3 ghid(64, 2);
    gemm_tc<<<gproj, 256, GEMM_DYN>>>(x, Wq, bq, qp, H_);
    gemm_tc<<<gproj, 256, GEMM_DYN>>>(x, Wk, bk, kp, H_);
    gemm_tc<<<gproj, 256, GEMM_DYN>>>(x, Wv, bv, vp, H_);
    gemm_tc<<<gproj, 256, GEMM_DYN>>>(x, Wg, bg, gp, H_);
    gemm_tc<<<ghid, 256, GEMM_DYN>>>(x, Wu1, bu1, hp, HID_);

    sigma_finish<<<B_ * M_, 256>>>(hp, Wu2, bu2, sig_out, isp);

    attn_kernel<<<dim3(32, 16, 8), 256, DYN>>>(qp, kp, vp, gp, isp, attn_out, pp);

    colsum_kernel<<<dim3(4, 8), 256>>>(pp, cp);
    zout_kernel<<<dim3(8, 8), 128>>>(cp, Wo, bo, z_out);
}

// round 11
// speedup vs baseline: 1.5653x; 1.3800x over previous
#include <cuda_runtime.h>
#include <cuda_bf16.h>
#include <cstdint>
#include <cstring>
#include <math.h>

#define B_   8
#define M_   1024
#define H_   1024
#define NH_  16
#define HD_  64
#define HID_ 256

// ---------------- scratch (device globals; no allocations allowed) ----------
__device__ float g_q[B_*M_*H_];
__device__ float g_k[B_*M_*H_];
__device__ float g_v[B_*M_*H_];
__device__ float g_g[B_*M_*H_];
__device__ float g_hid[B_*M_*HID_];
__device__ float g_invsig[B_*M_];
__device__ float g_partial[B_*32*H_];
__device__ float g_colsum[B_*H_];
// preconverted operands (packed bf16 pairs as unsigned words)
__device__ unsigned g_xhi[B_*M_*H_/2];            // X hi: [8192][512] words
__device__ unsigned g_xlo[B_*M_*H_/2];            // X lo
__device__ unsigned g_wthi[(4*H_ + HID_) * (H_/2)];  // W^T packed hi: [n][512]
__device__ unsigned g_wtlo[(4*H_ + HID_) * (H_/2)];  // W^T packed lo

// ============================================================================
// split (a,b) -> hi bf16 pair + lo residual bf16 pair (packed words)
// ============================================================================
__device__ __forceinline__ void split2(float a, float b, unsigned& hi, unsigned& lo) {
    __nv_bfloat162 h = __floats2bfloat162_rn(a, b);
    float ra = a - __low2float(h);
    float rb = b - __high2float(h);
    __nv_bfloat162 l = __floats2bfloat162_rn(ra, rb);
    unsigned uh, ul;
    memcpy(&uh, &h, 4);
    memcpy(&ul, &l, 4);
    hi = uh; lo = ul;
}

// ---------------- preconvert X (layout preserved, k-pairs packed) -----------
__global__ __launch_bounds__(256) void conv_x_kernel(
    const float* __restrict__ x, unsigned* __restrict__ xhi, unsigned* __restrict__ xlo)
{
    size_t i = (size_t)blockIdx.x * 256 + threadIdx.x;   // float4 index
    float4 v = ((const float4*)x)[i];
    unsigned h0, l0, h1, l1;
    split2(v.x, v.y, h0, l0);
    split2(v.z, v.w, h1, l1);
    uint2 h; h.x = h0; h.y = h1;
    uint2 l; l.x = l0; l.y = l1;
    ((uint2*)xhi)[i] = h;
    ((uint2*)xlo)[i] = l;
}

// ---------------- preconvert W: transpose + pack k-pairs --------------------
// out[n*512 + kp] = pack(bf(W[2kp][n]), bf(W[2kp+1][n]))
__global__ __launch_bounds__(256) void conv_w_kernel(
    const float* __restrict__ W, int Nc,
    unsigned* __restrict__ wh, unsigned* __restrict__ wl)
{
    int idx = blockIdx.x * 256 + threadIdx.x;
    int n = idx >> 9, kp = idx & 511;
    float a = W[(size_t)(2 * kp) * Nc + n];
    float b = W[(size_t)(2 * kp + 1) * Nc + n];
    unsigned h, l;
    split2(a, b, h, l);
    wh[idx] = h;
    wl[idx] = l;
}

// ============================================================================
// Tensor-core GEMM, split-bf16 3-term compensation, cp.async 2-stage pipeline.
// BM=128, BN=128, BK=32, 256 thr, warp tile 64x32, mma.m16n8k16.bf16, 2 CTA/SM
// ============================================================================
#define PITCH_B32 20
#define PITCH_B16 40
#define TILE_B32  (128 * PITCH_B32)   // 2560 words per tile
#define GEMM_DYN  (8 * TILE_B32 * 4)  // 2 stages x (Ahi,Alo,Bhi,Blo) = 81920 B

struct GArg  { const unsigned* wh; const unsigned* wl; const float* bias; float* out; };
struct GArg4 { GArg g[4]; };

__device__ __forceinline__ void ldm_x4(unsigned* r, unsigned addr) {
    asm volatile("ldmatrix.sync.aligned.m8n8.x4.shared.b16 {%0,%1,%2,%3}, [%4];\n"
        : "=r"(r[0]), "=r"(r[1]), "=r"(r[2]), "=r"(r[3]) : "r"(addr));
}

__device__ __forceinline__ void mma16816(float* d, const unsigned* a,
                                         unsigned b0, unsigned b1) {
    asm volatile(
        "mma.sync.aligned.m16n8k16.row.col.f32.bf16.bf16.f32 "
        "{%0,%1,%2,%3}, {%4,%5,%6,%7}, {%8,%9}, {%0,%1,%2,%3};\n"
        : "+f"(d[0]), "+f"(d[1]), "+f"(d[2]), "+f"(d[3])
        : "r"(a[0]), "r"(a[1]), "r"(a[2]), "r"(a[3]), "r"(b0), "r"(b1));
}

// stage one BK=32 slab (all 4 tiles) via cp.async; one commit group
__device__ __forceinline__ void stage_cp(
    int buf, int kc, int tid, unsigned sbase,
    const unsigned* baseAh, const unsigned* baseAl,
    const unsigned* baseBh, const unsigned* baseBl)
{
#pragma unroll
    for (int i = 0; i < 8; i++) {
        int id = i * 256 + tid;
        int tile = id >> 9;
        int rem = id & 511;
        int row = rem >> 2, c4 = rem & 3;
        const unsigned* bp = (tile == 0) ? baseAh
                           : (tile == 1) ? baseAl
                           : (tile == 2) ? baseBh : baseBl;
        const unsigned* src = bp + (size_t)row * 512 + kc * 16 + c4 * 4;
        unsigned dst = sbase +
            (unsigned)(((buf * 4 + tile) * TILE_B32 + row * PITCH_B32 + c4 * 4) * 4);
        asm volatile("cp.async.ca.shared.global [%0], [%1], 16;\n" :: "r"(dst), "l"(src));
    }
    asm volatile("cp.async.commit_group;\n");
}

__global__ __launch_bounds__(256, 2) void gemm_tc2(
    const unsigned* __restrict__ xhi, const unsigned* __restrict__ xlo,
    GArg4 args, int Nc)
{
    extern __shared__ unsigned smw[];
    const int tid = threadIdx.x;
    const int lane = tid & 31, warp = tid >> 5;
    const int wm = warp >> 2, wn = warp & 3;
    const int r0 = blockIdx.x * 128, n0 = blockIdx.y * 128;
    GArg ga = args.g[blockIdx.z];

    const unsigned sbase = (unsigned)__cvta_generic_to_shared(smw);
    const unsigned* baseAh = xhi + (size_t)r0 * 512;
    const unsigned* baseAl = xlo + (size_t)r0 * 512;
    const unsigned* baseBh = ga.wh + (size_t)n0 * 512;
    const unsigned* baseBl = ga.wl + (size_t)n0 * 512;

    const unsigned a_lane = (unsigned)((lane & 15) * PITCH_B16 + (lane >> 4) * 8);
    const unsigned b_lane = (unsigned)(((lane & 7) + ((lane >> 4) & 1) * 8) * PITCH_B16
                                       + ((lane >> 3) & 1) * 8);

    float acc[4][4][4];
#pragma unroll
    for (int i = 0; i < 4; i++)
#pragma unroll
        for (int j = 0; j < 4; j++)
#pragma unroll
            for (int c = 0; c < 4; c++) acc[i][j][c] = 0.f;

    stage_cp(0, 0, tid, sbase, baseAh, baseAl, baseBh, baseBl);

    for (int kc = 0; kc < 32; kc++) {
        const int cur = kc & 1;
        if (kc < 31) {
            stage_cp(cur ^ 1, kc + 1, tid, sbase, baseAh, baseAl, baseBh, baseBl);
            asm volatile("cp.async.wait_group 1;\n");
        } else {
            asm volatile("cp.async.wait_group 0;\n");
        }
        __syncthreads();

        const unsigned obAh = (unsigned)((cur * 4 + 0) * TILE_B32 * 4);
        const unsigned obAl = (unsigned)((cur * 4 + 1) * TILE_B32 * 4);
        const unsigned obBh = (unsigned)((cur * 4 + 2) * TILE_B32 * 4);
        const unsigned obBl = (unsigned)((cur * 4 + 3) * TILE_B32 * 4);

#pragma unroll
        for (int ks = 0; ks < 2; ks++) {
            unsigned af[4][4], bfr[2][4];
            const unsigned kso = (unsigned)(ks * 16);
            // --- Ahi x Bhi ---
#pragma unroll
            for (int mt = 0; mt < 4; mt++)
                ldm_x4(af[mt], sbase + obAh +
                       (a_lane + (unsigned)((wm * 64 + mt * 16) * PITCH_B16) + kso) * 2);
#pragma unroll
            for (int np = 0; np < 2; np++)
                ldm_x4(bfr[np], sbase + obBh +
                       (b_lane + (unsigned)((wn * 32 + np * 16) * PITCH_B16) + kso) * 2);
#pragma unroll
            for (int mt = 0; mt < 4; mt++)
#pragma unroll
                for (int nt = 0; nt < 4; nt++)
                    mma16816(acc[mt][nt], af[mt],
                             bfr[nt >> 1][(nt & 1) * 2], bfr[nt >> 1][(nt & 1) * 2 + 1]);
            // --- Ahi x Blo ---
#pragma unroll
            for (int np = 0; np < 2; np++)
                ldm_x4(bfr[np], sbase + obBl +
                       (b_lane + (unsigned)((wn * 32 + np * 16) * PITCH_B16) + kso) * 2);
#pragma unroll
            for (int mt = 0; mt < 4; mt++)
#pragma unroll
                for (int nt = 0; nt < 4; nt++)
                    mma16816(acc[mt][nt], af[mt],
                             bfr[nt >> 1][(nt & 1) * 2], bfr[nt >> 1][(nt & 1) * 2 + 1]);
            // --- Alo x Bhi ---
#pragma unroll
            for (int mt = 0; mt < 4; mt++)
                ldm_x4(af[mt], sbase + obAl +
                       (a_lane + (unsigned)((wm * 64 + mt * 16) * PITCH_B16) + kso) * 2);
#pragma unroll
            for (int np = 0; np < 2; np++)
                ldm_x4(bfr[np], sbase + obBh +
                       (b_lane + (unsigned)((wn * 32 + np * 16) * PITCH_B16) + kso) * 2);
#pragma unroll
            for (int mt = 0; mt < 4; mt++)
#pragma unroll
                for (int nt = 0; nt < 4; nt++)
                    mma16816(acc[mt][nt], af[mt],
                             bfr[nt >> 1][(nt & 1) * 2], bfr[nt >> 1][(nt & 1) * 2 + 1]);
        }
        __syncthreads();
    }

    // epilogue: bias + store
    const int gg = lane >> 2, tg = lane & 3;
#pragma unroll
    for (int mt = 0; mt < 4; mt++) {
#pragma unroll
        for (int nt = 0; nt < 4; nt++) {
            int row = r0 + wm * 64 + mt * 16 + gg;
            int col = n0 + wn * 32 + nt * 8 + tg * 2;
            float bx = ga.bias[col], by = ga.bias[col + 1];
            float2 o0; o0.x = acc[mt][nt][0] + bx; o0.y = acc[mt][nt][1] + by;
            float2 o1; o1.x = acc[mt][nt][2] + bx; o1.y = acc[mt][nt][3] + by;
            *(float2*)(ga.out + (size_t)row * Nc + col) = o0;
            *(float2*)(ga.out + (size_t)(row + 8) * Nc + col) = o1;
        }
    }
}

// ---------------- sigma: softplus(relu(hid) @ Wu2 + bu2) + 1e-6 -------------
__global__ __launch_bounds__(256) void sigma_finish(
    const float* __restrict__ hid, const float* __restrict__ Wu2,
    const float* __restrict__ bu2, float* __restrict__ sig_out,
    float* __restrict__ invsig)
{
    const int row = blockIdx.x, t = threadIdx.x;
    __shared__ float red[256];
    float h = hid[(size_t)row * HID_ + t];
    red[t] = fmaxf(h, 0.f) * Wu2[t];
    __syncthreads();
    for (int s = 128; s > 0; s >>= 1) {
        if (t < s) red[t] += red[t + s];
        __syncthreads();
    }
    if (t == 0) {
        float tv = red[0] + bu2[0];
        float sp = (tv > 0.f) ? tv + log1pf(expf(-tv)) : log1pf(expf(tv));
        float sg = sp + 1e-6f;
        sig_out[row] = sg;
        invsig[row] = 1.f / sg;
    }
}

// ---------------- fused attention: scores -> softmax -> attn out + ctx*g ----
#define SP  1032
#define KSP 257

__global__ __launch_bounds__(256) void attn_kernel(
    const float* __restrict__ qb, const float* __restrict__ kb,
    const float* __restrict__ vb, const float* __restrict__ gb,
    const float* __restrict__ invsig,
    float* __restrict__ attn_out, float* __restrict__ partial)
{
    extern __shared__ float smdyn[];
    float* ss = smdyn;
    float* qs = ss + 32 * SP;
    float* kv = qs + 32 * 64;
    __shared__ float ism[32];
    __shared__ float isn[M_];

    const int mt = blockIdx.x, h = blockIdx.y, b = blockIdx.z;
    const int m0 = mt * 32;
    const int tid = threadIdx.x;

    for (int i = tid; i < 32 * 16; i += 256) {
        int m = i >> 4, f = i & 15;
        *(float4*)(qs + m * 64 + f * 4) =
            *(const float4*)(qb + (((size_t)(b * M_ + m0 + m)) * NH_ + h) * HD_ + f * 4);
    }
    if (tid < 32) ism[tid] = invsig[b * M_ + m0 + tid];
    for (int i = tid; i < M_; i += 256) isn[i] = invsig[b * M_ + i];

    const int tn5 = tid & 31;
    const int tmq = tid >> 5;

    for (int nc = 0; nc < 4; nc++) {
        const int nb = nc * 256;
        for (int it = 0; it < 16; it++) {
            int idx = tid + 256 * it;
            int n = idx >> 4, f = idx & 15;
            float4 kx = *(const float4*)(kb + (((size_t)(b * M_ + nb + n)) * NH_ + h) * HD_ + f * 4);
            kv[(f*4+0)*KSP + n] = kx.x;
            kv[(f*4+1)*KSP + n] = kx.y;
            kv[(f*4+2)*KSP + n] = kx.z;
            kv[(f*4+3)*KSP + n] = kx.w;
        }
        __syncthreads();
        float acc[4][8];
#pragma unroll
        for (int i = 0; i < 4; i++)
#pragma unroll
            for (int j = 0; j < 8; j++) acc[i][j] = 0.f;
#pragma unroll 8
        for (int d = 0; d < 64; d++) {
            float a[4], bb[8];
#pragma unroll
            for (int i = 0; i < 4; i++) a[i] = qs[(tmq + 8*i) * 64 + d];
#pragma unroll
            for (int j = 0; j < 8; j++) bb[j] = kv[d * KSP + tn5 + 32*j];
#pragma unroll
            for (int i = 0; i < 4; i++)
#pragma unroll
                for (int j = 0; j < 8; j++)
                    acc[i][j] = fmaf(a[i], bb[j], acc[i][j]);
        }
#pragma unroll
        for (int i = 0; i < 4; i++) {
            int m = tmq + 8*i;
            float sm_ = 0.125f * ism[m];
#pragma unroll
            for (int j = 0; j < 8; j++) {
                int n = tn5 + 32*j;
                ss[m * SP + nb + n] = acc[i][j] * sm_ * isn[nb + n];
            }
        }
        __syncthreads();
    }

    const int warp = tid >> 5, lane = tid & 31;
    for (int rr = 0; rr < 4; rr++) {
        int m = warp + 8 * rr;
        float* row = ss + m * SP;
        float mx = -1e30f;
#pragma unroll
        for (int i = 0; i < 32; i++) mx = fmaxf(mx, row[lane + 32*i]);
        for (int o = 16; o > 0; o >>= 1) mx = fmaxf(mx, __shfl_xor_sync(0xffffffffu, mx, o));
        float sum = 0.f;
#pragma unroll
        for (int i = 0; i < 32; i++) {
            float e = __expf(row[lane + 32*i] - mx);
            row[lane + 32*i] = e;
            sum += e;
        }
        for (int o = 16; o > 0; o >>= 1) sum += __shfl_xor_sync(0xffffffffu, sum, o);
        float inv = 1.f / sum;
        float* orow = attn_out + (((size_t)(b * NH_ + h)) * M_ + m0 + m) * M_;
#pragma unroll
        for (int c = 0; c < 8; c++) {
            float4 v4 = *(float4*)(row + c*128 + lane*4);
            v4.x *= inv; v4.y *= inv; v4.z *= inv; v4.w *= inv;
            *(float4*)(row + c*128 + lane*4) = v4;
            *(float4*)(orow + c*128 + lane*4) = v4;
        }
    }
    __syncthreads();

    const int td = tid & 15;
    const int tmm = tid >> 4;
    float4 a0 = {0.f,0.f,0.f,0.f}, a1 = {0.f,0.f,0.f,0.f};
    for (int nc = 0; nc < 4; nc++) {
        const int nb = nc * 256;
        for (int it = 0; it < 16; it++) {
            int idx = tid + 256 * it;
            int n = idx >> 4, f = idx & 15;
            *(float4*)(kv + n * 64 + f * 4) =
                *(const float4*)(vb + (((size_t)(b * M_ + nb + n)) * NH_ + h) * HD_ + f * 4);
        }
        __syncthreads();
        for (int n = 0; n < 256; n++) {
            float s0 = ss[tmm * SP + nb + n];
            float s1 = ss[(tmm + 16) * SP + nb + n];
            float4 vv = *(float4*)(kv + n * 64 + td * 4);
            a0.x = fmaf(s0, vv.x, a0.x); a0.y = fmaf(s0, vv.y, a0.y);
            a0.z = fmaf(s0, vv.z, a0.z); a0.w = fmaf(s0, vv.w, a0.w);
            a1.x = fmaf(s1, vv.x, a1.x); a1.y = fmaf(s1, vv.y, a1.y);
            a1.z = fmaf(s1, vv.z, a1.z); a1.w = fmaf(s1, vv.w, a1.w);
        }
        __syncthreads();
    }

    {
        float4 g0 = *(const float4*)(gb + (((size_t)(b * M_ + m0 + tmm))      * NH_ + h) * HD_ + td * 4);
        float4 g1 = *(const float4*)(gb + (((size_t)(b * M_ + m0 + tmm + 16)) * NH_ + h) * HD_ + td * 4);
        g0.x = 1.f / (1.f + __expf(-g0.x)); g0.y = 1.f / (1.f + __expf(-g0.y));
        g0.z = 1.f / (1.f + __expf(-g0.z)); g0.w = 1.f / (1.f + __expf(-g0.w));
        g1.x = 1.f / (1.f + __expf(-g1.x)); g1.y = 1.f / (1.f + __expf(-g1.y));
        g1.z = 1.f / (1.f + __expf(-g1.z)); g1.w = 1.f / (1.f + __expf(-g1.w));
        a0.x *= g0.x; a0.y *= g0.y; a0.z *= g0.z; a0.w *= g0.w;
        a1.x *= g1.x; a1.y *= g1.y; a1.z *= g1.z; a1.w *= g1.w;
        *(float4*)(qs + tmm * 64 + td * 4) = a0;
        *(float4*)(qs + (tmm + 16) * 64 + td * 4) = a1;
    }
    __syncthreads();
    if (tid < 64) {
        float s = 0.f;
#pragma unroll
        for (int m = 0; m < 32; m++) s += qs[m * 64 + tid];
        partial[((size_t)(b * 32 + mt)) * H_ + h * 64 + tid] = s;
    }
}

// ---------------- column-sum reduce (mean over m) ---------------------------
__global__ __launch_bounds__(256) void colsum_kernel(
    const float* __restrict__ partial, float* __restrict__ colsum)
{
    int b = blockIdx.y;
    int c = blockIdx.x * 256 + threadIdx.x;
    float s = 0.f;
#pragma unroll
    for (int t = 0; t < 32; t++) s += partial[((size_t)(b * 32 + t)) * H_ + c];
    colsum[b * H_ + c] = s * (1.f / 1024.f);
}

// ---------------- z = mean @ Wo + bo ----------------------------------------
__global__ __launch_bounds__(128) void zout_kernel(
    const float* __restrict__ colsum, const float* __restrict__ Wo,
    const float* __restrict__ bo, float* __restrict__ z)
{
    int b = blockIdx.y;
    int n = blockIdx.x * 128 + threadIdx.x;
    __shared__ float cs[H_];
    for (int i = threadIdx.x; i < H_; i += 128) cs[i] = colsum[b * H_ + i];
    __syncthreads();
    float acc = bo[n];
    for (int i = 0; i < H_; i++) acc = fmaf(cs[i], Wo[(size_t)i * H_ + n], acc);
    z[b * H_ + n] = acc;
}

// ---------------------------------------------------------------------------
extern "C" void kernel_launch(void* const* d_in, const int* in_sizes, int n_in,
                              void* d_out, int out_size)
{
    const float* x   = (const float*)d_in[0];
    const float* Wq  = (const float*)d_in[1];
    const float* bq  = (const float*)d_in[2];
    const float* Wk  = (const float*)d_in[3];
    const float* bk  = (const float*)d_in[4];
    const float* Wv  = (const float*)d_in[5];
    const float* bv  = (const float*)d_in[6];
    const float* Wg  = (const float*)d_in[7];
    const float* bg  = (const float*)d_in[8];
    const float* Wo  = (const float*)d_in[9];
    const float* bo  = (const float*)d_in[10];
    const float* Wu1 = (const float*)d_in[11];
    const float* bu1 = (const float*)d_in[12];
    const float* Wu2 = (const float*)d_in[13];
    const float* bu2 = (const float*)d_in[14];

    float* out      = (float*)d_out;
    float* z_out    = out;                                  // [8,1024]
    float* attn_out = out + B_ * H_;                        // [8,16,1024,1024]
    float* sig_out  = out + (size_t)out_size - B_ * M_;     // [8,1024]

    float *qp, *kp, *vp, *gp, *hp, *isp, *pp, *cp;
    unsigned *xhip, *xlop, *wthip, *wtlop;
    cudaGetSymbolAddress((void**)&qp, g_q);
    cudaGetSymbolAddress((void**)&kp, g_k);
    cudaGetSymbolAddress((void**)&vp, g_v);
    cudaGetSymbolAddress((void**)&gp, g_g);
    cudaGetSymbolAddress((void**)&hp, g_hid);
    cudaGetSymbolAddress((void**)&isp, g_invsig);
    cudaGetSymbolAddress((void**)&pp, g_partial);
    cudaGetSymbolAddress((void**)&cp, g_colsum);
    cudaGetSymbolAddress((void**)&xhip, g_xhi);
    cudaGetSymbolAddress((void**)&xlop, g_xlo);
    cudaGetSymbolAddress((void**)&wthip, g_wthi);
    cudaGetSymbolAddress((void**)&wtlop, g_wtlo);

    const int DYN = (32 * SP + 32 * 64 + 64 * KSP) * (int)sizeof(float); // 206080 B
    cudaFuncSetAttribute(attn_kernel, cudaFuncAttributeMaxDynamicSharedMemorySize, DYN);
    cudaFuncSetAttribute(gemm_tc2, cudaFuncAttributeMaxDynamicSharedMemorySize, GEMM_DYN);

    const size_t WROW = H_ / 2;  // 512 words per output row
    // ---- preconvert X and weights ----
    conv_x_kernel<<<B_*M_*H_/4/256, 256>>>(x, xhip, xlop);
    conv_w_kernel<<<2*H_, 256>>>(Wq,  H_,   wthip + 0*H_*WROW, wtlop + 0*H_*WROW);
    conv_w_kernel<<<2*H_, 256>>>(Wk,  H_,   wthip + 1*H_*WROW, wtlop + 1*H_*WROW);
    conv_w_kernel<<<2*H_, 256>>>(Wv,  H_,   wthip + 2*H_*WROW, wtlop + 2*H_*WROW);
    conv_w_kernel<<<2*H_, 256>>>(Wg,  H_,   wthip + 3*H_*WROW, wtlop + 3*H_*WROW);
    conv_w_kernel<<<2*HID_, 256>>>(Wu1, HID_, wthip + 4*H_*WROW, wtlop + 4*H_*WROW);

    // ---- fused projection GEMMs (q,k,v,g) ----
    GArg4 a4;
    a4.g[0].wh = wthip + 0*H_*WROW; a4.g[0].wl = wtlop + 0*H_*WROW; a4.g[0].bias = bq; a4.g[0].out = qp;
    a4.g[1].wh = wthip + 1*H_*WROW; a4.g[1].wl = wtlop + 1*H_*WROW; a4.g[1].bias = bk; a4.g[1].out = kp;
    a4.g[2].wh = wthip + 2*H_*WROW; a4.g[2].wl = wtlop + 2*H_*WROW; a4.g[2].bias = bv; a4.g[2].out = vp;
    a4.g[3].wh = wthip + 3*H_*WROW; a4.g[3].wl = wtlop + 3*H_*WROW; a4.g[3].bias = bg; a4.g[3].out = gp;
    gemm_tc2<<<dim3(64, 8, 4), 256, GEMM_DYN>>>(xhip, xlop, a4, H_);

    // ---- sigma hidden GEMM ----
    GArg4 au;
    au.g[0].wh = wthip + 4*H_*WROW; au.g[0].wl = wtlop + 4*H_*WROW; au.g[0].bias = bu1; au.g[0].out = hp;
    au.g[1] = au.g[0]; au.g[2] = au.g[0]; au.g[3] = au.g[0];
    gemm_tc2<<<dim3(64, 2, 1), 256, GEMM_DYN>>>(xhip, xlop, au, HID_);

    sigma_finish<<<B_ * M_, 256>>>(hp, Wu2, bu2, sig_out, isp);

    attn_kernel<<<dim3(32, 16, 8), 256, DYN>>>(qp, kp, vp, gp, isp, attn_out, pp);

    colsum_kernel<<<dim3(4, 8), 256>>>(pp, cp);
    zout_kernel<<<dim3(8, 8), 128>>>(cp, Wo, bo, z_out);
}

// round 12
// speedup vs baseline: 1.6966x; 1.0838x over previous
#include <cuda_runtime.h>
#include <cuda_bf16.h>
#include <cstdint>
#include <cstring>
#include <math.h>

#define B_   8
#define M_   1024
#define H_   1024
#define NH_  16
#define HD_  64
#define HID_ 256

// ---------------- scratch (device globals; no allocations allowed) ----------
__device__ float g_v[B_*M_*H_];
__device__ float g_g[B_*M_*H_];
__device__ float g_hid[B_*M_*HID_];
__device__ float g_invsig[B_*M_];
__device__ float g_partial[B_*32*H_];
__device__ float g_colsum[B_*H_];
// preconverted operands (packed bf16 pairs as unsigned words)
__device__ unsigned g_xhi[B_*M_*H_/2];
__device__ unsigned g_xlo[B_*M_*H_/2];
__device__ unsigned g_wthi[(4*H_ + HID_) * (H_/2)];
__device__ unsigned g_wtlo[(4*H_ + HID_) * (H_/2)];
// q/k projections stored packed (d-pairs) for attention MMA
__device__ unsigned g_qhi[B_*M_*H_/2];
__device__ unsigned g_qlo[B_*M_*H_/2];
__device__ unsigned g_khi[B_*M_*H_/2];
__device__ unsigned g_klo[B_*M_*H_/2];

// ============================================================================
__device__ __forceinline__ void split2(float a, float b, unsigned& hi, unsigned& lo) {
    __nv_bfloat162 h = __floats2bfloat162_rn(a, b);
    float ra = a - __low2float(h);
    float rb = b - __high2float(h);
    __nv_bfloat162 l = __floats2bfloat162_rn(ra, rb);
    unsigned uh, ul;
    memcpy(&uh, &h, 4);
    memcpy(&ul, &l, 4);
    hi = uh; lo = ul;
}

__global__ __launch_bounds__(256) void conv_x_kernel(
    const float* __restrict__ x, unsigned* __restrict__ xhi, unsigned* __restrict__ xlo)
{
    size_t i = (size_t)blockIdx.x * 256 + threadIdx.x;
    float4 v = ((const float4*)x)[i];
    unsigned h0, l0, h1, l1;
    split2(v.x, v.y, h0, l0);
    split2(v.z, v.w, h1, l1);
    uint2 h; h.x = h0; h.y = h1;
    uint2 l; l.x = l0; l.y = l1;
    ((uint2*)xhi)[i] = h;
    ((uint2*)xlo)[i] = l;
}

__global__ __launch_bounds__(256) void conv_w_kernel(
    const float* __restrict__ W, int Nc,
    unsigned* __restrict__ wh, unsigned* __restrict__ wl)
{
    int idx = blockIdx.x * 256 + threadIdx.x;
    int n = idx >> 9, kp = idx & 511;
    float a = W[(size_t)(2 * kp) * Nc + n];
    float b = W[(size_t)(2 * kp + 1) * Nc + n];
    unsigned h, l;
    split2(a, b, h, l);
    wh[idx] = h;
    wl[idx] = l;
}

// ============================================================================
// Tensor-core GEMM (unchanged pipeline), epilogue optionally emits packed bf16
// ============================================================================
#define PITCH_B32 20
#define PITCH_B16 40
#define TILE_B32  (128 * PITCH_B32)
#define GEMM_DYN  (8 * TILE_B32 * 4)

struct GArg  { const unsigned* wh; const unsigned* wl; const float* bias;
               float* out; unsigned* ohi; unsigned* olo; int packed; };
struct GArg4 { GArg g[4]; };

__device__ __forceinline__ void ldm_x4(unsigned* r, unsigned addr) {
    asm volatile("ldmatrix.sync.aligned.m8n8.x4.shared.b16 {%0,%1,%2,%3}, [%4];\n"
        : "=r"(r[0]), "=r"(r[1]), "=r"(r[2]), "=r"(r[3]) : "r"(addr));
}

__device__ __forceinline__ void mma16816(float* d, const unsigned* a,
                                         unsigned b0, unsigned b1) {
    asm volatile(
        "mma.sync.aligned.m16n8k16.row.col.f32.bf16.bf16.f32 "
        "{%0,%1,%2,%3}, {%4,%5,%6,%7}, {%8,%9}, {%0,%1,%2,%3};\n"
        : "+f"(d[0]), "+f"(d[1]), "+f"(d[2]), "+f"(d[3])
        : "r"(a[0]), "r"(a[1]), "r"(a[2]), "r"(a[3]), "r"(b0), "r"(b1));
}

__device__ __forceinline__ void stage_cp(
    int buf, int kc, int tid, unsigned sbase,
    const unsigned* baseAh, const unsigned* baseAl,
    const unsigned* baseBh, const unsigned* baseBl)
{
#pragma unroll
    for (int i = 0; i < 8; i++) {
        int id = i * 256 + tid;
        int tile = id >> 9;
        int rem = id & 511;
        int row = rem >> 2, c4 = rem & 3;
        const unsigned* bp = (tile == 0) ? baseAh
                           : (tile == 1) ? baseAl
                           : (tile == 2) ? baseBh : baseBl;
        const unsigned* src = bp + (size_t)row * 512 + kc * 16 + c4 * 4;
        unsigned dst = sbase +
            (unsigned)(((buf * 4 + tile) * TILE_B32 + row * PITCH_B32 + c4 * 4) * 4);
        asm volatile("cp.async.ca.shared.global [%0], [%1], 16;\n" :: "r"(dst), "l"(src));
    }
    asm volatile("cp.async.commit_group;\n");
}

__global__ __launch_bounds__(256, 2) void gemm_tc2(
    const unsigned* __restrict__ xhi, const unsigned* __restrict__ xlo,
    GArg4 args, int Nc)
{
    extern __shared__ unsigned smw[];
    const int tid = threadIdx.x;
    const int lane = tid & 31, warp = tid >> 5;
    const int wm = warp >> 2, wn = warp & 3;
    const int r0 = blockIdx.x * 128, n0 = blockIdx.y * 128;
    GArg ga = args.g[blockIdx.z];

    const unsigned sbase = (unsigned)__cvta_generic_to_shared(smw);
    const unsigned* baseAh = xhi + (size_t)r0 * 512;
    const unsigned* baseAl = xlo + (size_t)r0 * 512;
    const unsigned* baseBh = ga.wh + (size_t)n0 * 512;
    const unsigned* baseBl = ga.wl + (size_t)n0 * 512;

    const unsigned a_lane = (unsigned)((lane & 15) * PITCH_B16 + (lane >> 4) * 8);
    const unsigned b_lane = (unsigned)(((lane & 7) + ((lane >> 4) & 1) * 8) * PITCH_B16
                                       + ((lane >> 3) & 1) * 8);

    float acc[4][4][4];
#pragma unroll
    for (int i = 0; i < 4; i++)
#pragma unroll
        for (int j = 0; j < 4; j++)
#pragma unroll
            for (int c = 0; c < 4; c++) acc[i][j][c] = 0.f;

    stage_cp(0, 0, tid, sbase, baseAh, baseAl, baseBh, baseBl);

    for (int kc = 0; kc < 32; kc++) {
        const int cur = kc & 1;
        if (kc < 31) {
            stage_cp(cur ^ 1, kc + 1, tid, sbase, baseAh, baseAl, baseBh, baseBl);
            asm volatile("cp.async.wait_group 1;\n");
        } else {
            asm volatile("cp.async.wait_group 0;\n");
        }
        __syncthreads();

        const unsigned obAh = (unsigned)((cur * 4 + 0) * TILE_B32 * 4);
        const unsigned obAl = (unsigned)((cur * 4 + 1) * TILE_B32 * 4);
        const unsigned obBh = (unsigned)((cur * 4 + 2) * TILE_B32 * 4);
        const unsigned obBl = (unsigned)((cur * 4 + 3) * TILE_B32 * 4);

#pragma unroll
        for (int ks = 0; ks < 2; ks++) {
            unsigned af[4][4], bfr[2][4];
            const unsigned kso = (unsigned)(ks * 16);
#pragma unroll
            for (int mt = 0; mt < 4; mt++)
                ldm_x4(af[mt], sbase + obAh +
                       (a_lane + (unsigned)((wm * 64 + mt * 16) * PITCH_B16) + kso) * 2);
#pragma unroll
            for (int np = 0; np < 2; np++)
                ldm_x4(bfr[np], sbase + obBh +
                       (b_lane + (unsigned)((wn * 32 + np * 16) * PITCH_B16) + kso) * 2);
#pragma unroll
            for (int mt = 0; mt < 4; mt++)
#pragma unroll
                for (int nt = 0; nt < 4; nt++)
                    mma16816(acc[mt][nt], af[mt],
                             bfr[nt >> 1][(nt & 1) * 2], bfr[nt >> 1][(nt & 1) * 2 + 1]);
#pragma unroll
            for (int np = 0; np < 2; np++)
                ldm_x4(bfr[np], sbase + obBl +
                       (b_lane + (unsigned)((wn * 32 + np * 16) * PITCH_B16) + kso) * 2);
#pragma unroll
            for (int mt = 0; mt < 4; mt++)
#pragma unroll
                for (int nt = 0; nt < 4; nt++)
                    mma16816(acc[mt][nt], af[mt],
                             bfr[nt >> 1][(nt & 1) * 2], bfr[nt >> 1][(nt & 1) * 2 + 1]);
#pragma unroll
            for (int mt = 0; mt < 4; mt++)
                ldm_x4(af[mt], sbase + obAl +
                       (a_lane + (unsigned)((wm * 64 + mt * 16) * PITCH_B16) + kso) * 2);
#pragma unroll
            for (int np = 0; np < 2; np++)
                ldm_x4(bfr[np], sbase + obBh +
                       (b_lane + (unsigned)((wn * 32 + np * 16) * PITCH_B16) + kso) * 2);
#pragma unroll
            for (int mt = 0; mt < 4; mt++)
#pragma unroll
                for (int nt = 0; nt < 4; nt++)
                    mma16816(acc[mt][nt], af[mt],
                             bfr[nt >> 1][(nt & 1) * 2], bfr[nt >> 1][(nt & 1) * 2 + 1]);
        }
        __syncthreads();
    }

    const int gg = lane >> 2, tg = lane & 3;
#pragma unroll
    for (int mt = 0; mt < 4; mt++) {
#pragma unroll
        for (int nt = 0; nt < 4; nt++) {
            int row = r0 + wm * 64 + mt * 16 + gg;
            int col = n0 + wn * 32 + nt * 8 + tg * 2;
            float bx = ga.bias[col], by = ga.bias[col + 1];
            float v0x = acc[mt][nt][0] + bx, v0y = acc[mt][nt][1] + by;
            float v1x = acc[mt][nt][2] + bx, v1y = acc[mt][nt][3] + by;
            if (ga.packed) {
                unsigned h0, l0, h1, l1;
                split2(v0x, v0y, h0, l0);
                split2(v1x, v1y, h1, l1);
                size_t w0 = (size_t)row * (Nc >> 1) + (col >> 1);
                size_t w1 = (size_t)(row + 8) * (Nc >> 1) + (col >> 1);
                ga.ohi[w0] = h0; ga.olo[w0] = l0;
                ga.ohi[w1] = h1; ga.olo[w1] = l1;
            } else {
                float2 o0; o0.x = v0x; o0.y = v0y;
                float2 o1; o1.x = v1x; o1.y = v1y;
                *(float2*)(ga.out + (size_t)row * Nc + col) = o0;
                *(float2*)(ga.out + (size_t)(row + 8) * Nc + col) = o1;
            }
        }
    }
}

// ---------------- sigma ------------------------------------------------------
__global__ __launch_bounds__(256) void sigma_finish(
    const float* __restrict__ hid, const float* __restrict__ Wu2,
    const float* __restrict__ bu2, float* __restrict__ sig_out,
    float* __restrict__ invsig)
{
    const int row = blockIdx.x, t = threadIdx.x;
    __shared__ float red[256];
    float h = hid[(size_t)row * HID_ + t];
    red[t] = fmaxf(h, 0.f) * Wu2[t];
    __syncthreads();
    for (int s = 128; s > 0; s >>= 1) {
        if (t < s) red[t] += red[t + s];
        __syncthreads();
    }
    if (t == 0) {
        float tv = red[0] + bu2[0];
        float sp = (tv > 0.f) ? tv + log1pf(expf(-tv)) : log1pf(expf(tv));
        float sg = sp + 1e-6f;
        sig_out[row] = sg;
        invsig[row] = 1.f / sg;
    }
}

// ============================================================================
// Tensor-core fused attention
//   scores (MMA, compensated) -> softmax (fp32, exact) -> attn out
//   -> attn@V (MMA, compensated) -> sigmoid(g)*ctx column sums
// ============================================================================
#define SP    1032
#define SS_W  (32*SP)             // 33024 words: fp32 score tile
#define QH_W  SS_W                // [32][36] words
#define QL_W  (QH_W + 32*36)
#define KB_W  (QL_W + 32*36)      // 35328: K double buffer
#define KHALF (128*36)            // khi half of one buffer (words)
#define KBUF_W (2*KHALF)          // 9216 per buffer
#define VTH_W KB_W                // reuse K region: [64][68] words
#define VTL_W (VTH_W + 64*68)
#define CTX_W (VTL_W + 64*68)     // [32][68] fp32
#define ATTN_DYN ((KB_W + 2*KBUF_W) * 4)   // 215040 B

__device__ __forceinline__ void attn_stage_k(
    const unsigned* __restrict__ khi, const unsigned* __restrict__ klo,
    int b, int h, int chunk, int buf, int tid, unsigned sbase)
{
#pragma unroll
    for (int it = 0; it < 8; it++) {
        int id = it * 256 + tid;
        int arr = id >> 10;           // 0: hi, 1: lo
        int rem = id & 1023;
        int row = rem >> 3, gr = rem & 7;
        const unsigned* src = (arr ? klo : khi)
            + (size_t)(b * M_ + chunk * 128 + row) * 512 + h * 32 + gr * 4;
        unsigned dst = sbase +
            (unsigned)((KB_W + buf * KBUF_W + arr * KHALF + row * 36 + gr * 4) * 4);
        asm volatile("cp.async.ca.shared.global [%0], [%1], 16;\n" :: "r"(dst), "l"(src));
    }
    asm volatile("cp.async.commit_group;\n");
}

__global__ __launch_bounds__(256) void attn_tc(
    const unsigned* __restrict__ qhi, const unsigned* __restrict__ qlo,
    const unsigned* __restrict__ khi, const unsigned* __restrict__ klo,
    const float* __restrict__ vb, const float* __restrict__ gb,
    const float* __restrict__ invsig,
    float* __restrict__ attn_out, float* __restrict__ partial)
{
    extern __shared__ unsigned smw[];
    float* ssf = (float*)smw;
    __shared__ float ism[32];
    __shared__ float isn[M_];

    const int mt = blockIdx.x, h = blockIdx.y, b = blockIdx.z;
    const int m0 = mt * 32;
    const int tid = threadIdx.x;
    const int lane = tid & 31, warp = tid >> 5;
    const int wm = warp >> 2, wn = warp & 3;         // wm 0..1, wn 0..3
    const unsigned sbase = (unsigned)__cvta_generic_to_shared(smw);

    if (tid < 32) ism[tid] = invsig[b * M_ + m0 + tid];
    for (int i = tid; i < M_; i += 256) isn[i] = invsig[b * M_ + i];

    // ---- stage Q tile (32 rows x 8 granules, hi + lo) ----
    {
        int row = tid >> 3, gr = tid & 7;
        size_t gw = (size_t)(b * M_ + m0 + row) * 512 + h * 32 + gr * 4;
        unsigned dh = sbase + (unsigned)((QH_W + row * 36 + gr * 4) * 4);
        unsigned dl = sbase + (unsigned)((QL_W + row * 36 + gr * 4) * 4);
        asm volatile("cp.async.ca.shared.global [%0], [%1], 16;\n" :: "r"(dh), "l"(qhi + gw));
        asm volatile("cp.async.ca.shared.global [%0], [%1], 16;\n" :: "r"(dl), "l"(qlo + gw));
    }
    asm volatile("cp.async.commit_group;\n");
    attn_stage_k(khi, klo, b, h, 0, 0, tid, sbase);

    const unsigned a_lane = (unsigned)((lane & 15) * 72 + (lane >> 4) * 8);  // b16 units
    const unsigned b_lane = (unsigned)(((lane & 7) + ((lane >> 4) & 1) * 8) * 72
                                       + ((lane >> 3) & 1) * 8);

    // ---- phase 1: scores via MMA, 8 chunks of 128 n ----
    for (int c = 0; c < 8; c++) {
        if (c < 7) {
            attn_stage_k(khi, klo, b, h, c + 1, (c + 1) & 1, tid, sbase);
            asm volatile("cp.async.wait_group 1;\n");
        } else {
            asm volatile("cp.async.wait_group 0;\n");
        }
        __syncthreads();

        const unsigned kh_b = (unsigned)((KB_W + (c & 1) * KBUF_W) * 4);
        const unsigned kl_b = kh_b + (unsigned)(KHALF * 4);
        const unsigned qh_b = (unsigned)(QH_W * 4);
        const unsigned ql_b = (unsigned)(QL_W * 4);

        float acc[4][4];
#pragma unroll
        for (int i = 0; i < 4; i++)
#pragma unroll
            for (int j = 0; j < 4; j++) acc[i][j] = 0.f;

#pragma unroll
        for (int ks = 0; ks < 4; ks++) {
            const unsigned kso = (unsigned)(ks * 16);
            unsigned ah[4], al[4], bh[2][4], bl[2][4];
            ldm_x4(ah, sbase + qh_b + (a_lane + (unsigned)(wm * 16 * 72) + kso) * 2);
            ldm_x4(al, sbase + ql_b + (a_lane + (unsigned)(wm * 16 * 72) + kso) * 2);
#pragma unroll
            for (int np = 0; np < 2; np++) {
                unsigned ro = (unsigned)((wn * 32 + np * 16) * 72);
                ldm_x4(bh[np], sbase + kh_b + (b_lane + ro + kso) * 2);
                ldm_x4(bl[np], sbase + kl_b + (b_lane + ro + kso) * 2);
            }
#pragma unroll
            for (int nt = 0; nt < 4; nt++) {
                unsigned h0 = bh[nt >> 1][(nt & 1) * 2], h1 = bh[nt >> 1][(nt & 1) * 2 + 1];
                unsigned l0 = bl[nt >> 1][(nt & 1) * 2], l1 = bl[nt >> 1][(nt & 1) * 2 + 1];
                mma16816(acc[nt], ah, h0, h1);
                mma16816(acc[nt], ah, l0, l1);
                mma16816(acc[nt], al, h0, h1);
            }
        }
        // write scaled scores to ss
        {
            int r = wm * 16 + (lane >> 2);
            float s0 = 0.125f * ism[r], s1 = 0.125f * ism[r + 8];
#pragma unroll
            for (int nt = 0; nt < 4; nt++) {
                int col = c * 128 + wn * 32 + nt * 8 + (lane & 3) * 2;
                float2 w0; w0.x = acc[nt][0] * s0 * isn[col];
                w0.y = acc[nt][1] * s0 * isn[col + 1];
                float2 w1; w1.x = acc[nt][2] * s1 * isn[col];
                w1.y = acc[nt][3] * s1 * isn[col + 1];
                *(float2*)&ssf[r * SP + col] = w0;
                *(float2*)&ssf[(r + 8) * SP + col] = w1;
            }
        }
        __syncthreads();
    }

    // ---- phase 2: softmax per row + attn gmem write (unchanged) ----
    for (int rr = 0; rr < 4; rr++) {
        int m = warp + 8 * rr;
        float* row = ssf + m * SP;
        float mx = -1e30f;
#pragma unroll
        for (int i = 0; i < 32; i++) mx = fmaxf(mx, row[lane + 32 * i]);
        for (int o = 16; o > 0; o >>= 1) mx = fmaxf(mx, __shfl_xor_sync(0xffffffffu, mx, o));
        float sum = 0.f;
#pragma unroll
        for (int i = 0; i < 32; i++) {
            float e = __expf(row[lane + 32 * i] - mx);
            row[lane + 32 * i] = e;
            sum += e;
        }
        for (int o = 16; o > 0; o >>= 1) sum += __shfl_xor_sync(0xffffffffu, sum, o);
        float inv = 1.f / sum;
        float* orow = attn_out + (((size_t)(b * NH_ + h)) * M_ + m0 + m) * M_;
#pragma unroll
        for (int cc = 0; cc < 8; cc++) {
            float4 v4 = *(float4*)(row + cc * 128 + lane * 4);
            v4.x *= inv; v4.y *= inv; v4.z *= inv; v4.w *= inv;
            *(float4*)(row + cc * 128 + lane * 4) = v4;
            *(float4*)(orow + cc * 128 + lane * 4) = v4;
        }
    }

    // ---- phase 3: ctx = attn @ V via MMA (A from fp32 ss, B staged per chunk)
    float ctx[2][4];
#pragma unroll
    for (int i = 0; i < 2; i++)
#pragma unroll
        for (int j = 0; j < 4; j++) ctx[i][j] = 0.f;

    for (int c = 0; c < 8; c++) {
        __syncthreads();   // protect Vt region from previous chunk readers
        // stage Vt: [64 d][64 npair] hi/lo words, packed along n-pairs
#pragma unroll
        for (int u = 0; u < 4; u++) {
            int uu = u * 256 + tid;
            int np = uu & 63, dq = uu >> 6;      // dq 0..15, d = dq*4
            int d = dq * 4;
            size_t gbase = (size_t)(b * M_ + c * 128 + 2 * np) * H_ + h * 64 + d;
            float4 v0 = *(const float4*)(vb + gbase);
            float4 v1 = *(const float4*)(vb + gbase + H_);
            unsigned hw, lw;
            split2(v0.x, v1.x, hw, lw);
            smw[VTH_W + (d + 0) * 68 + np] = hw; smw[VTL_W + (d + 0) * 68 + np] = lw;
            split2(v0.y, v1.y, hw, lw);
            smw[VTH_W + (d + 1) * 68 + np] = hw; smw[VTL_W + (d + 1) * 68 + np] = lw;
            split2(v0.z, v1.z, hw, lw);
            smw[VTH_W + (d + 2) * 68 + np] = hw; smw[VTL_W + (d + 2) * 68 + np] = lw;
            split2(v0.w, v1.w, hw, lw);
            smw[VTH_W + (d + 3) * 68 + np] = hw; smw[VTL_W + (d + 3) * 68 + np] = lw;
        }
        __syncthreads();

#pragma unroll
        for (int ks = 0; ks < 8; ks++) {
            int kn = c * 128 + ks * 16;
            int r = wm * 16 + (lane >> 2);
            int k0 = kn + (lane & 3) * 2;
            float2 f0 = *(float2*)&ssf[r * SP + k0];
            float2 f1 = *(float2*)&ssf[(r + 8) * SP + k0];
            float2 f2 = *(float2*)&ssf[r * SP + k0 + 8];
            float2 f3 = *(float2*)&ssf[(r + 8) * SP + k0 + 8];
            unsigned ah[4], al[4];
            split2(f0.x, f0.y, ah[0], al[0]);
            split2(f1.x, f1.y, ah[1], al[1]);
            split2(f2.x, f2.y, ah[2], al[2]);
            split2(f3.x, f3.y, ah[3], al[3]);
            int dr = wn * 16 + (lane >> 2);
            int wb = ks * 8 + (lane & 3);
            unsigned bh0 = smw[VTH_W + dr * 68 + wb];
            unsigned bh1 = smw[VTH_W + dr * 68 + wb + 4];
            unsigned bh2 = smw[VTH_W + (dr + 8) * 68 + wb];
            unsigned bh3 = smw[VTH_W + (dr + 8) * 68 + wb + 4];
            unsigned bl0 = smw[VTL_W + dr * 68 + wb];
            unsigned bl1 = smw[VTL_W + dr * 68 + wb + 4];
            unsigned bl2 = smw[VTL_W + (dr + 8) * 68 + wb];
            unsigned bl3 = smw[VTL_W + (dr + 8) * 68 + wb + 4];
            mma16816(ctx[0], ah, bh0, bh1);
            mma16816(ctx[1], ah, bh2, bh3);
            mma16816(ctx[0], ah, bl0, bl1);
            mma16816(ctx[1], ah, bl2, bl3);
            mma16816(ctx[0], al, bh0, bh1);
            mma16816(ctx[1], al, bh2, bh3);
        }
    }

    // ---- write ctx to smem tile, then sigmoid(g)-weighted column sums ----
    __syncthreads();
    {
        float* ctxt = (float*)(smw + CTX_W);
        int r = wm * 16 + (lane >> 2);
        int cb = wn * 16 + (lane & 3) * 2;
        float2 w;
        w.x = ctx[0][0]; w.y = ctx[0][1]; *(float2*)&ctxt[r * 68 + cb] = w;
        w.x = ctx[0][2]; w.y = ctx[0][3]; *(float2*)&ctxt[(r + 8) * 68 + cb] = w;
        w.x = ctx[1][0]; w.y = ctx[1][1]; *(float2*)&ctxt[r * 68 + cb + 8] = w;
        w.x = ctx[1][2]; w.y = ctx[1][3]; *(float2*)&ctxt[(r + 8) * 68 + cb + 8] = w;
    }
    __syncthreads();
    if (tid < 64) {
        float* ctxt = (float*)(smw + CTX_W);
        float s = 0.f;
#pragma unroll
        for (int m = 0; m < 32; m++) {
            float cv = ctxt[m * 68 + tid];
            float gv = gb[(size_t)(b * M_ + m0 + m) * H_ + h * 64 + tid];
            s += cv / (1.f + __expf(-gv));
        }
        partial[((size_t)(b * 32 + mt)) * H_ + h * 64 + tid] = s;
    }
}

// ---------------- column-sum reduce (mean over m) ---------------------------
__global__ __launch_bounds__(256) void colsum_kernel(
    const float* __restrict__ partial, float* __restrict__ colsum)
{
    int b = blockIdx.y;
    int c = blockIdx.x * 256 + threadIdx.x;
    float s = 0.f;
#pragma unroll
    for (int t = 0; t < 32; t++) s += partial[((size_t)(b * 32 + t)) * H_ + c];
    colsum[b * H_ + c] = s * (1.f / 1024.f);
}

// ---------------- z = mean @ Wo + bo ----------------------------------------
__global__ __launch_bounds__(128) void zout_kernel(
    const float* __restrict__ colsum, const float* __restrict__ Wo,
    const float* __restrict__ bo, float* __restrict__ z)
{
    int b = blockIdx.y;
    int n = blockIdx.x * 128 + threadIdx.x;
    __shared__ float cs[H_];
    for (int i = threadIdx.x; i < H_; i += 128) cs[i] = colsum[b * H_ + i];
    __syncthreads();
    float acc = bo[n];
    for (int i = 0; i < H_; i++) acc = fmaf(cs[i], Wo[(size_t)i * H_ + n], acc);
    z[b * H_ + n] = acc;
}

// ---------------------------------------------------------------------------
extern "C" void kernel_launch(void* const* d_in, const int* in_sizes, int n_in,
                              void* d_out, int out_size)
{
    const float* x   = (const float*)d_in[0];
    const float* Wq  = (const float*)d_in[1];
    const float* bq  = (const float*)d_in[2];
    const float* Wk  = (const float*)d_in[3];
    const float* bk  = (const float*)d_in[4];
    const float* Wv  = (const float*)d_in[5];
    const float* bv  = (const float*)d_in[6];
    const float* Wg  = (const float*)d_in[7];
    const float* bg  = (const float*)d_in[8];
    const float* Wo  = (const float*)d_in[9];
    const float* bo  = (const float*)d_in[10];
    const float* Wu1 = (const float*)d_in[11];
    const float* bu1 = (const float*)d_in[12];
    const float* Wu2 = (const float*)d_in[13];
    const float* bu2 = (const float*)d_in[14];

    float* out      = (float*)d_out;
    float* z_out    = out;
    float* attn_out = out + B_ * H_;
    float* sig_out  = out + (size_t)out_size - B_ * M_;

    float *vp, *gp, *hp, *isp, *pp, *cp;
    unsigned *xhip, *xlop, *wthip, *wtlop, *qhip, *qlop, *khip, *klop;
    cudaGetSymbolAddress((void**)&vp, g_v);
    cudaGetSymbolAddress((void**)&gp, g_g);
    cudaGetSymbolAddress((void**)&hp, g_hid);
    cudaGetSymbolAddress((void**)&isp, g_invsig);
    cudaGetSymbolAddress((void**)&pp, g_partial);
    cudaGetSymbolAddress((void**)&cp, g_colsum);
    cudaGetSymbolAddress((void**)&xhip, g_xhi);
    cudaGetSymbolAddress((void**)&xlop, g_xlo);
    cudaGetSymbolAddress((void**)&wthip, g_wthi);
    cudaGetSymbolAddress((void**)&wtlop, g_wtlo);
    cudaGetSymbolAddress((void**)&qhip, g_qhi);
    cudaGetSymbolAddress((void**)&qlop, g_qlo);
    cudaGetSymbolAddress((void**)&khip, g_khi);
    cudaGetSymbolAddress((void**)&klop, g_klo);

    cudaFuncSetAttribute(attn_tc, cudaFuncAttributeMaxDynamicSharedMemorySize, ATTN_DYN);
    cudaFuncSetAttribute(gemm_tc2, cudaFuncAttributeMaxDynamicSharedMemorySize, GEMM_DYN);

    const size_t WROW = H_ / 2;
    conv_x_kernel<<<B_*M_*H_/4/256, 256>>>(x, xhip, xlop);
    conv_w_kernel<<<2*H_, 256>>>(Wq,  H_,   wthip + 0*H_*WROW, wtlop + 0*H_*WROW);
    conv_w_kernel<<<2*H_, 256>>>(Wk,  H_,   wthip + 1*H_*WROW, wtlop + 1*H_*WROW);
    conv_w_kernel<<<2*H_, 256>>>(Wv,  H_,   wthip + 2*H_*WROW, wtlop + 2*H_*WROW);
    conv_w_kernel<<<2*H_, 256>>>(Wg,  H_,   wthip + 3*H_*WROW, wtlop + 3*H_*WROW);
    conv_w_kernel<<<2*HID_, 256>>>(Wu1, HID_, wthip + 4*H_*WROW, wtlop + 4*H_*WROW);

    GArg4 a4;
    a4.g[0].wh = wthip + 0*H_*WROW; a4.g[0].wl = wtlop + 0*H_*WROW; a4.g[0].bias = bq;
    a4.g[0].out = nullptr; a4.g[0].ohi = qhip; a4.g[0].olo = qlop; a4.g[0].packed = 1;
    a4.g[1].wh = wthip + 1*H_*WROW; a4.g[1].wl = wtlop + 1*H_*WROW; a4.g[1].bias = bk;
    a4.g[1].out = nullptr; a4.g[1].ohi = khip; a4.g[1].olo = klop; a4.g[1].packed = 1;
    a4.g[2].wh = wthip + 2*H_*WROW; a4.g[2].wl = wtlop + 2*H_*WROW; a4.g[2].bias = bv;
    a4.g[2].out = vp; a4.g[2].ohi = nullptr; a4.g[2].olo = nullptr; a4.g[2].packed = 0;
    a4.g[3].wh = wthip + 3*H_*WROW; a4.g[3].wl = wtlop + 3*H_*WROW; a4.g[3].bias = bg;
    a4.g[3].out = gp; a4.g[3].ohi = nullptr; a4.g[3].olo = nullptr; a4.g[3].packed = 0;
    gemm_tc2<<<dim3(64, 8, 4), 256, GEMM_DYN>>>(xhip, xlop, a4, H_);

    GArg4 au;
    au.g[0].wh = wthip + 4*H_*WROW; au.g[0].wl = wtlop + 4*H_*WROW; au.g[0].bias = bu1;
    au.g[0].out = hp; au.g[0].ohi = nullptr; au.g[0].olo = nullptr; au.g[0].packed = 0;
    au.g[1] = au.g[0]; au.g[2] = au.g[0]; au.g[3] = au.g[0];
    gemm_tc2<<<dim3(64, 2, 1), 256, GEMM_DYN>>>(xhip, xlop, au, HID_);

    sigma_finish<<<B_ * M_, 256>>>(hp, Wu2, bu2, sig_out, isp);

    attn_tc<<<dim3(32, 16, 8), 256, ATTN_DYN>>>(qhip, qlop, khip, klop,
                                                vp, gp, isp, attn_out, pp);

    colsum_kernel<<<dim3(4, 8), 256>>>(pp, cp);
    zout_kernel<<<dim3(8, 8), 128>>>(cp, Wo, bo, z_out);
}